// round 3
// baseline (speedup 1.0000x reference)
#include <cuda_runtime.h>
#include <math.h>

#define NN   50000
#define INC  128
#define C0   128      // HEADS*HID
#define OUTC 64
#define EMAX 800000
#define NEG  0.2f

// ---------------- scratch (static device globals; no allocation) ------------
__device__ __align__(16) int   g_deg[NN];
__device__ __align__(16) int   g_off[NN + 4];
__device__ __align__(16) int   g_cur[NN];
__device__ __align__(16) int   g_csr[EMAX];
__device__ __align__(16) float g_h0[(size_t)NN * C0];
__device__ __align__(16) float g_as0[NN * 2];
__device__ __align__(16) float g_ad0[NN * 2];
__device__ __align__(16) float g_agg0[(size_t)NN * C0];
__device__ __align__(16) float g_bnsum[C0];
__device__ __align__(16) float g_bnsq[C0];
__device__ __align__(16) float g_scale[C0];
__device__ __align__(16) float g_shift[C0];
__device__ __align__(16) float g_h1[(size_t)NN * OUTC];
__device__ __align__(16) float g_a1s[NN];
__device__ __align__(16) float g_a1d[NN];

// ---------------- CSR build -------------------------------------------------
__global__ void k_zero() {
    int i = blockIdx.x * blockDim.x + threadIdx.x;
    if (i < NN) g_deg[i] = 0;
    if (i < C0) { g_bnsum[i] = 0.f; g_bnsq[i] = 0.f; }
}

// edge_index is int32 (JAX x64 disabled => randint returns int32).
__global__ void k_count(const int* __restrict__ ei, int E) {
    int i = blockIdx.x * blockDim.x + threadIdx.x;
    if (i < E) {
        int d = ei[E + i];
        if (d >= 0 && d < NN) atomicAdd(&g_deg[d], 1);
    }
}

__global__ void k_scan() {
    __shared__ int part[1024];
    int t = threadIdx.x;
    const int chunk = (NN + 1023) / 1024;
    int beg = t * chunk;
    int end = min(beg + chunk, NN);
    int s = 0;
    for (int i = beg; i < end; i++) s += g_deg[i];
    part[t] = s;
    __syncthreads();
    for (int d = 1; d < 1024; d <<= 1) {
        int v = 0;
        if (t >= d) v = part[t - d];
        __syncthreads();
        part[t] += v;
        __syncthreads();
    }
    int base = (t == 0) ? 0 : part[t - 1];
    for (int i = beg; i < end; i++) {
        g_off[i] = base; g_cur[i] = base; base += g_deg[i];
    }
    if (t == 1023) g_off[NN] = part[1023];
}

__global__ void k_scatter(const int* __restrict__ ei, int E) {
    int i = blockIdx.x * blockDim.x + threadIdx.x;
    if (i < E) {
        int d = ei[E + i];
        int s = ei[i];
        if (d >= 0 && d < NN && s >= 0 && s < NN) {
            int p = atomicAdd(&g_cur[d], 1);
            g_csr[p] = s;
        }
    }
}

// ---------------- SGEMM (K = 128 fixed) -------------------------------------
// BNCOLS in {128, 64}.  TRANS: A is g_agg0 with fused BatchNorm+ELU on load.
template <int BNCOLS, bool TRANS>
__global__ __launch_bounds__(256) void k_gemm(const float* __restrict__ Ax,
                                              const float* __restrict__ W,
                                              int nrows) {
    const int TN = BNCOLS / 16;          // 8 or 4
    __shared__ float As[8][128];
    __shared__ float Bs[8][BNCOLS];
    const float* A = TRANS ? g_agg0 : Ax;
    float* Cp = (BNCOLS == 128) ? g_h0 : g_h1;

    int tid = threadIdx.x;
    int row0 = blockIdx.x * 128;
    int ty = tid / 16, tx = tid % 16;
    float acc[8][TN];
#pragma unroll
    for (int i = 0; i < 8; i++)
#pragma unroll
        for (int j = 0; j < TN; j++) acc[i][j] = 0.f;

    for (int kk = 0; kk < 128; kk += 8) {
        // A tile: 128 rows x 8 k
        {
            int ar = tid >> 1;
            int ak = (tid & 1) * 4;
            int grow = row0 + ar;
            float4 v = make_float4(0.f, 0.f, 0.f, 0.f);
            if (grow < nrows)
                v = *(const float4*)&A[(size_t)grow * 128 + kk + ak];
            if (TRANS) {
                int c = kk + ak;
                float t0 = v.x * g_scale[c] + g_shift[c];
                float t1 = v.y * g_scale[c + 1] + g_shift[c + 1];
                float t2 = v.z * g_scale[c + 2] + g_shift[c + 2];
                float t3 = v.w * g_scale[c + 3] + g_shift[c + 3];
                v.x = t0 > 0.f ? t0 : expm1f(t0);
                v.y = t1 > 0.f ? t1 : expm1f(t1);
                v.z = t2 > 0.f ? t2 : expm1f(t2);
                v.w = t3 > 0.f ? t3 : expm1f(t3);
            }
            As[ak + 0][ar] = v.x; As[ak + 1][ar] = v.y;
            As[ak + 2][ar] = v.z; As[ak + 3][ar] = v.w;
        }
        // W tile: 8 x BNCOLS
        if (BNCOLS == 128) {
            int bk = tid >> 5, bc = (tid & 31) * 4;
            float4 v = *(const float4*)&W[(size_t)(kk + bk) * BNCOLS + bc];
            *(float4*)&Bs[bk][bc] = v;
        } else {
            int bk = tid >> 5, bc = (tid & 31) * 2;
            float2 v = *(const float2*)&W[(size_t)(kk + bk) * BNCOLS + bc];
            Bs[bk][bc] = v.x; Bs[bk][bc + 1] = v.y;
        }
        __syncthreads();
#pragma unroll
        for (int k = 0; k < 8; k++) {
            float ra[8], rb[TN];
#pragma unroll
            for (int i = 0; i < 8; i++) ra[i] = As[k][ty * 8 + i];
#pragma unroll
            for (int j = 0; j < TN; j++) rb[j] = Bs[k][tx * TN + j];
#pragma unroll
            for (int i = 0; i < 8; i++)
#pragma unroll
                for (int j = 0; j < TN; j++) acc[i][j] = fmaf(ra[i], rb[j], acc[i][j]);
        }
        __syncthreads();
    }
#pragma unroll
    for (int i = 0; i < 8; i++) {
        int r = row0 + ty * 8 + i;
        if (r < nrows) {
#pragma unroll
            for (int j = 0; j < TN; j += 4) {
                float4 v = make_float4(acc[i][j], acc[i][j + 1], acc[i][j + 2], acc[i][j + 3]);
                *(float4*)&Cp[(size_t)r * BNCOLS + tx * TN + j] = v;
            }
        }
    }
}

// ---------------- attention logits ------------------------------------------
__global__ void k_att0(const float* __restrict__ att_s, const float* __restrict__ att_d) {
    int warp = (blockIdx.x * blockDim.x + threadIdx.x) >> 5;
    int lane = threadIdx.x & 31;
    if (warp >= NN) return;
    float4 v = *(const float4*)&g_h0[(size_t)warp * 128 + lane * 4];
    float4 s4 = *(const float4*)&att_s[lane * 4];
    float4 d4 = *(const float4*)&att_d[lane * 4];
    float ps = v.x * s4.x + v.y * s4.y + v.z * s4.z + v.w * s4.w;
    float pd = v.x * d4.x + v.y * d4.y + v.z * d4.z + v.w * d4.w;
#pragma unroll
    for (int o = 8; o; o >>= 1) {
        ps += __shfl_down_sync(0xffffffffu, ps, o, 16);
        pd += __shfl_down_sync(0xffffffffu, pd, o, 16);
    }
    if ((lane & 15) == 0) {
        g_as0[warp * 2 + (lane >> 4)] = ps;
        g_ad0[warp * 2 + (lane >> 4)] = pd;
    }
}

__global__ void k_att1(const float* __restrict__ att_s, const float* __restrict__ att_d) {
    int warp = (blockIdx.x * blockDim.x + threadIdx.x) >> 5;
    int lane = threadIdx.x & 31;
    if (warp >= NN) return;
    float2 v = *(const float2*)&g_h1[(size_t)warp * 64 + lane * 2];
    float2 s2 = *(const float2*)&att_s[lane * 2];
    float2 d2 = *(const float2*)&att_d[lane * 2];
    float ps = v.x * s2.x + v.y * s2.y;
    float pd = v.x * d2.x + v.y * d2.y;
#pragma unroll
    for (int o = 16; o; o >>= 1) {
        ps += __shfl_down_sync(0xffffffffu, ps, o);
        pd += __shfl_down_sync(0xffffffffu, pd, o);
    }
    if (lane == 0) { g_a1s[warp] = ps; g_a1d[warp] = pd; }
}

// ---------------- per-node softmax + aggregation (warp per node) ------------
__device__ __forceinline__ float lrelu(float x) { return x > 0.f ? x : NEG * x; }

__global__ void k_agg0(const float* __restrict__ bias0) {
    int warp = (blockIdx.x * blockDim.x + threadIdx.x) >> 5;
    int lane = threadIdx.x & 31;
    if (warp >= NN) return;
    int n = warp;
    int beg = g_off[n], end = g_off[n + 1];
    float2 ad = *(const float2*)&g_ad0[n * 2];
    float2 an = *(const float2*)&g_as0[n * 2];

    float d0 = 0.f, d1 = 0.f;
    for (int i = beg + lane; i < end; i += 32) {
        int s = g_csr[i];
        float2 a = *(const float2*)&g_as0[s * 2];
        d0 += expf(lrelu(a.x + ad.x));
        d1 += expf(lrelu(a.y + ad.y));
    }
#pragma unroll
    for (int o = 16; o; o >>= 1) {
        d0 += __shfl_down_sync(0xffffffffu, d0, o);
        d1 += __shfl_down_sync(0xffffffffu, d1, o);
    }
    d0 = __shfl_sync(0xffffffffu, d0, 0);
    d1 = __shfl_sync(0xffffffffu, d1, 0);
    float es0 = lrelu(an.x + ad.x);
    float es1 = lrelu(an.y + ad.y);
    d0 += expf(es0);
    d1 += expf(es1);
    float inv0 = 1.f / (d0 + 1e-16f);
    float inv1 = 1.f / (d1 + 1e-16f);

    bool head1 = lane >= 16;
    int coff = lane * 4;
    float invh = head1 ? inv1 : inv0;
    float4 acc = make_float4(0.f, 0.f, 0.f, 0.f);
    for (int i = beg; i < end; i++) {
        int s = g_csr[i];
        float2 a = *(const float2*)&g_as0[s * 2];
        float e = head1 ? (a.y + ad.y) : (a.x + ad.x);
        float w = expf(lrelu(e)) * invh;
        float4 hv = *(const float4*)&g_h0[(size_t)s * 128 + coff];
        acc.x = fmaf(hv.x, w, acc.x); acc.y = fmaf(hv.y, w, acc.y);
        acc.z = fmaf(hv.z, w, acc.z); acc.w = fmaf(hv.w, w, acc.w);
    }
    { // self loop
        float w = expf(head1 ? es1 : es0) * invh;
        float4 hv = *(const float4*)&g_h0[(size_t)n * 128 + coff];
        acc.x = fmaf(hv.x, w, acc.x); acc.y = fmaf(hv.y, w, acc.y);
        acc.z = fmaf(hv.z, w, acc.z); acc.w = fmaf(hv.w, w, acc.w);
    }
    float4 b = *(const float4*)&bias0[coff];
    acc.x += b.x; acc.y += b.y; acc.z += b.z; acc.w += b.w;
    *(float4*)&g_agg0[(size_t)n * 128 + coff] = acc;
}

__global__ void k_agg1(const float* __restrict__ bias1, float* __restrict__ out) {
    int warp = (blockIdx.x * blockDim.x + threadIdx.x) >> 5;
    int lane = threadIdx.x & 31;
    if (warp >= NN) return;
    int n = warp;
    int beg = g_off[n], end = g_off[n + 1];
    float ad = g_a1d[n];
    float an = g_a1s[n];

    float d = 0.f;
    for (int i = beg + lane; i < end; i += 32)
        d += expf(lrelu(g_a1s[g_csr[i]] + ad));
#pragma unroll
    for (int o = 16; o; o >>= 1) d += __shfl_down_sync(0xffffffffu, d, o);
    d = __shfl_sync(0xffffffffu, d, 0);
    float es = lrelu(an + ad);
    d += expf(es);
    float inv = 1.f / (d + 1e-16f);

    int coff = lane * 2;
    float2 acc = make_float2(0.f, 0.f);
    for (int i = beg; i < end; i++) {
        int s = g_csr[i];
        float w = expf(lrelu(g_a1s[s] + ad)) * inv;
        float2 hv = *(const float2*)&g_h1[(size_t)s * 64 + coff];
        acc.x = fmaf(hv.x, w, acc.x);
        acc.y = fmaf(hv.y, w, acc.y);
    }
    { // self loop
        float w = expf(es) * inv;
        float2 hv = *(const float2*)&g_h1[(size_t)n * 64 + coff];
        acc.x = fmaf(hv.x, w, acc.x);
        acc.y = fmaf(hv.y, w, acc.y);
    }
    float2 b = *(const float2*)&bias1[coff];
    float2 r = make_float2(acc.x + b.x, acc.y + b.y);
    *(float2*)&out[(size_t)n * 64 + coff] = r;
}

// ---------------- BatchNorm stats -------------------------------------------
__global__ void k_bnstats() {
    int c = threadIdx.x;   // 128 threads
    float s = 0.f, q = 0.f;
    for (int r = blockIdx.x; r < NN; r += gridDim.x) {
        float v = g_agg0[(size_t)r * 128 + c];
        s += v; q += v * v;
    }
    atomicAdd(&g_bnsum[c], s);
    atomicAdd(&g_bnsq[c], q);
}

__global__ void k_bnfinal(const float* __restrict__ gamma, const float* __restrict__ beta) {
    int c = threadIdx.x;
    float mu = g_bnsum[c] / (float)NN;
    float var = g_bnsq[c] / (float)NN - mu * mu;
    float sc = gamma[c] * rsqrtf(var + 1e-5f);
    g_scale[c] = sc;
    g_shift[c] = beta[c] - mu * sc;
}

// ---------------- launch ----------------------------------------------------
extern "C" void kernel_launch(void* const* d_in, const int* in_sizes, int n_in,
                              void* d_out, int out_size) {
    const float* data = (const float*)d_in[0];
    const int*   ei   = (const int*)d_in[1];    // int32! (JAX x64 disabled)
    const float* W0   = (const float*)d_in[2];
    const float* as0  = (const float*)d_in[3];
    const float* ad0  = (const float*)d_in[4];
    const float* b0   = (const float*)d_in[5];
    const float* g0   = (const float*)d_in[6];
    const float* be0  = (const float*)d_in[7];
    const float* W1   = (const float*)d_in[8];
    const float* as1  = (const float*)d_in[9];
    const float* ad1  = (const float*)d_in[10];
    const float* b1   = (const float*)d_in[11];
    float* out = (float*)d_out;

    int E = in_sizes[1] / 2;
    if (E > EMAX) E = EMAX;

    int warpBlocks = (NN * 32 + 255) / 256;

    k_zero<<<(NN + 255) / 256, 256>>>();
    k_count<<<(E + 255) / 256, 256>>>(ei, E);
    k_scan<<<1, 1024>>>();
    k_scatter<<<(E + 255) / 256, 256>>>(ei, E);

    k_gemm<128, false><<<(NN + 127) / 128, 256>>>(data, W0, NN);
    k_att0<<<warpBlocks, 256>>>(as0, ad0);
    k_agg0<<<warpBlocks, 256>>>(b0);

    k_bnstats<<<512, 128>>>();
    k_bnfinal<<<1, 128>>>(g0, be0);

    k_gemm<64, true><<<(NN + 127) / 128, 256>>>(nullptr, W1, NN);
    k_att1<<<warpBlocks, 256>>>(as1, ad1);
    k_agg1<<<warpBlocks, 256>>>(b1, out);
}

// round 4
// speedup vs baseline: 1.0596x; 1.0596x over previous
#include <cuda_runtime.h>
#include <math.h>

#define NN   50000
#define C0   128      // HEADS*HID
#define OUTC 64
#define EMAX 800000
#define NEG  0.2f

// ---------------- scratch (static device globals; no allocation) ------------
__device__ __align__(16) int   g_deg[NN];
__device__ __align__(16) int   g_off[NN + 4];
__device__ __align__(16) int   g_cur[NN];
__device__ __align__(16) int   g_csr[EMAX];
__device__ __align__(16) float g_h0[(size_t)NN * C0];
__device__ __align__(16) float g_as0[NN * 2];
__device__ __align__(16) float g_ad0[NN * 2];
__device__ __align__(16) float g_agg0[(size_t)NN * C0];
__device__ __align__(16) float g_bnsum[C0];
__device__ __align__(16) float g_bnsq[C0];
__device__ __align__(16) float g_scale[C0];
__device__ __align__(16) float g_shift[C0];
__device__ __align__(16) float g_h1[(size_t)NN * OUTC];
__device__ __align__(16) float g_a1s[NN];
__device__ __align__(16) float g_a1d[NN];

// ---------------- CSR build -------------------------------------------------
__global__ void k_zero() {
    int i = blockIdx.x * blockDim.x + threadIdx.x;
    if (i < NN) g_deg[i] = 0;
    if (i < C0) { g_bnsum[i] = 0.f; g_bnsq[i] = 0.f; }
}

__global__ void k_count(const int* __restrict__ ei, int E) {
    int i = blockIdx.x * blockDim.x + threadIdx.x;
    if (i < E) {
        int d = ei[E + i];
        if (d >= 0 && d < NN) atomicAdd(&g_deg[d], 1);
    }
}

__global__ void k_scan() {
    __shared__ int part[1024];
    int t = threadIdx.x;
    const int chunk = (NN + 1023) / 1024;
    int beg = t * chunk;
    int end = min(beg + chunk, NN);
    int s = 0;
    for (int i = beg; i < end; i++) s += g_deg[i];
    part[t] = s;
    __syncthreads();
    for (int d = 1; d < 1024; d <<= 1) {
        int v = 0;
        if (t >= d) v = part[t - d];
        __syncthreads();
        part[t] += v;
        __syncthreads();
    }
    int base = (t == 0) ? 0 : part[t - 1];
    for (int i = beg; i < end; i++) {
        g_off[i] = base; g_cur[i] = base; base += g_deg[i];
    }
    if (t == 1023) g_off[NN] = part[1023];
}

__global__ void k_scatter(const int* __restrict__ ei, int E) {
    int i = blockIdx.x * blockDim.x + threadIdx.x;
    if (i < E) {
        int d = ei[E + i];
        int s = ei[i];
        if (d >= 0 && d < NN && s >= 0 && s < NN) {
            int p = atomicAdd(&g_cur[d], 1);
            g_csr[p] = s;
        }
    }
}

// ---------------- SGEMM (K = 128 fixed) + fused attention-logit epilogue ----
// BNCOLS=128: 2 heads of 64 ch -> g_as0/g_ad0.  BNCOLS=64: 1 head -> g_a1s/d.
// TRANS: A is g_agg0 with fused BatchNorm+ELU on load.
template <int BNCOLS, bool TRANS>
__global__ __launch_bounds__(256) void k_gemm(const float* __restrict__ Ax,
                                              const float* __restrict__ W,
                                              const float* __restrict__ att_s,
                                              const float* __restrict__ att_d,
                                              int nrows) {
    const int TN = BNCOLS / 16;          // 8 or 4
    __shared__ float As[8][128];
    __shared__ float Bs[8][BNCOLS];
    const float* A = TRANS ? g_agg0 : Ax;
    float* Cp = (BNCOLS == 128) ? g_h0 : g_h1;

    int tid = threadIdx.x;
    int row0 = blockIdx.x * 128;
    int ty = tid / 16, tx = tid % 16;
    float acc[8][TN];
#pragma unroll
    for (int i = 0; i < 8; i++)
#pragma unroll
        for (int j = 0; j < TN; j++) acc[i][j] = 0.f;

    for (int kk = 0; kk < 128; kk += 8) {
        {
            int ar = tid >> 1;
            int ak = (tid & 1) * 4;
            int grow = row0 + ar;
            float4 v = make_float4(0.f, 0.f, 0.f, 0.f);
            if (grow < nrows)
                v = *(const float4*)&A[(size_t)grow * 128 + kk + ak];
            if (TRANS) {
                int c = kk + ak;
                float t0 = v.x * g_scale[c] + g_shift[c];
                float t1 = v.y * g_scale[c + 1] + g_shift[c + 1];
                float t2 = v.z * g_scale[c + 2] + g_shift[c + 2];
                float t3 = v.w * g_scale[c + 3] + g_shift[c + 3];
                v.x = t0 > 0.f ? t0 : expm1f(t0);
                v.y = t1 > 0.f ? t1 : expm1f(t1);
                v.z = t2 > 0.f ? t2 : expm1f(t2);
                v.w = t3 > 0.f ? t3 : expm1f(t3);
            }
            As[ak + 0][ar] = v.x; As[ak + 1][ar] = v.y;
            As[ak + 2][ar] = v.z; As[ak + 3][ar] = v.w;
        }
        if (BNCOLS == 128) {
            int bk = tid >> 5, bc = (tid & 31) * 4;
            float4 v = *(const float4*)&W[(size_t)(kk + bk) * BNCOLS + bc];
            *(float4*)&Bs[bk][bc] = v;
        } else {
            int bk = tid >> 5, bc = (tid & 31) * 2;
            float2 v = *(const float2*)&W[(size_t)(kk + bk) * BNCOLS + bc];
            Bs[bk][bc] = v.x; Bs[bk][bc + 1] = v.y;
        }
        __syncthreads();
#pragma unroll
        for (int k = 0; k < 8; k++) {
            float ra[8], rb[TN];
#pragma unroll
            for (int i = 0; i < 8; i++) ra[i] = As[k][ty * 8 + i];
#pragma unroll
            for (int j = 0; j < TN; j++) rb[j] = Bs[k][tx * TN + j];
#pragma unroll
            for (int i = 0; i < 8; i++)
#pragma unroll
                for (int j = 0; j < TN; j++) acc[i][j] = fmaf(ra[i], rb[j], acc[i][j]);
        }
        __syncthreads();
    }

    // att vectors for this thread's column strip
    float vs[TN], vd[TN];
#pragma unroll
    for (int j = 0; j < TN; j++) {
        vs[j] = att_s[tx * TN + j];
        vd[j] = att_d[tx * TN + j];
    }

#pragma unroll
    for (int i = 0; i < 8; i++) {
        int r = row0 + ty * 8 + i;
        bool ok = (r < nrows);
        // store C row strip
        if (ok) {
#pragma unroll
            for (int j = 0; j < TN; j += 4) {
                float4 v = make_float4(acc[i][j], acc[i][j + 1], acc[i][j + 2], acc[i][j + 3]);
                *(float4*)&Cp[(size_t)r * BNCOLS + tx * TN + j] = v;
            }
        }
        // fused attention logits
        float ps = 0.f, pd = 0.f;
#pragma unroll
        for (int j = 0; j < TN; j++) {
            ps = fmaf(acc[i][j], vs[j], ps);
            pd = fmaf(acc[i][j], vd[j], pd);
        }
        if (BNCOLS == 128) {
            // 2 heads: reduce within 8-lane groups (tx 0..7 = head0, 8..15 = head1)
#pragma unroll
            for (int o = 4; o; o >>= 1) {
                ps += __shfl_down_sync(0xffffffffu, ps, o, 8);
                pd += __shfl_down_sync(0xffffffffu, pd, o, 8);
            }
            if (ok && (tx & 7) == 0) {
                g_as0[r * 2 + (tx >> 3)] = ps;
                g_ad0[r * 2 + (tx >> 3)] = pd;
            }
        } else {
            // 1 head: reduce across all 16 tx lanes
#pragma unroll
            for (int o = 8; o; o >>= 1) {
                ps += __shfl_down_sync(0xffffffffu, ps, o, 16);
                pd += __shfl_down_sync(0xffffffffu, pd, o, 16);
            }
            if (ok && tx == 0) {
                g_a1s[r] = ps;
                g_a1d[r] = pd;
            }
        }
    }
}

// ---------------- single-pass softmax-aggregate (warp per node) -------------
__device__ __forceinline__ float lrelu(float x) { return x > 0.f ? x : NEG * x; }

// layer-0: also accumulates BatchNorm statistics via block-level reduction
__global__ __launch_bounds__(256) void k_agg0(const float* __restrict__ bias0) {
    __shared__ float s_sum[C0];
    __shared__ float s_sq[C0];
    int tid = threadIdx.x;
    if (tid < C0) { s_sum[tid] = 0.f; s_sq[tid] = 0.f; }
    __syncthreads();

    int n = (blockIdx.x * blockDim.x + tid) >> 5;
    int lane = tid & 31;
    if (n < NN) {
        int beg = g_off[n], end = g_off[n + 1];
        float2 ad = *(const float2*)&g_ad0[n * 2];
        float2 an = *(const float2*)&g_as0[n * 2];
        bool head1 = lane >= 16;
        float adh = head1 ? ad.y : ad.x;
        float anh = head1 ? an.y : an.x;
        int coff = lane * 4;

        float d = 0.f;
        float4 acc = make_float4(0.f, 0.f, 0.f, 0.f);
        for (int i = beg; i < end; i++) {
            int s = g_csr[i];
            float2 a = *(const float2*)&g_as0[s * 2];
            float w = __expf(lrelu((head1 ? a.y : a.x) + adh));
            d += w;
            float4 hv = *(const float4*)&g_h0[(size_t)s * 128 + coff];
            acc.x = fmaf(hv.x, w, acc.x); acc.y = fmaf(hv.y, w, acc.y);
            acc.z = fmaf(hv.z, w, acc.z); acc.w = fmaf(hv.w, w, acc.w);
        }
        { // self loop
            float w = __expf(lrelu(anh + adh));
            d += w;
            float4 hv = *(const float4*)&g_h0[(size_t)n * 128 + coff];
            acc.x = fmaf(hv.x, w, acc.x); acc.y = fmaf(hv.y, w, acc.y);
            acc.z = fmaf(hv.z, w, acc.z); acc.w = fmaf(hv.w, w, acc.w);
        }
        float inv = 1.f / (d + 1e-16f);
        float4 b = *(const float4*)&bias0[coff];
        float4 o;
        o.x = acc.x * inv + b.x; o.y = acc.y * inv + b.y;
        o.z = acc.z * inv + b.z; o.w = acc.w * inv + b.w;
        *(float4*)&g_agg0[(size_t)n * 128 + coff] = o;

        // BN partials (block-local)
        atomicAdd(&s_sum[coff + 0], o.x); atomicAdd(&s_sq[coff + 0], o.x * o.x);
        atomicAdd(&s_sum[coff + 1], o.y); atomicAdd(&s_sq[coff + 1], o.y * o.y);
        atomicAdd(&s_sum[coff + 2], o.z); atomicAdd(&s_sq[coff + 2], o.z * o.z);
        atomicAdd(&s_sum[coff + 3], o.w); atomicAdd(&s_sq[coff + 3], o.w * o.w);
    }
    __syncthreads();
    if (tid < C0) {
        atomicAdd(&g_bnsum[tid], s_sum[tid]);
        atomicAdd(&g_bnsq[tid], s_sq[tid]);
    }
}

__global__ __launch_bounds__(256) void k_agg1(const float* __restrict__ bias1,
                                              float* __restrict__ out) {
    int n = (blockIdx.x * blockDim.x + threadIdx.x) >> 5;
    int lane = threadIdx.x & 31;
    if (n >= NN) return;
    int beg = g_off[n], end = g_off[n + 1];
    float ad = g_a1d[n];
    float an = g_a1s[n];
    int coff = lane * 2;

    float d = 0.f;
    float2 acc = make_float2(0.f, 0.f);
    for (int i = beg; i < end; i++) {
        int s = g_csr[i];
        float w = __expf(lrelu(g_a1s[s] + ad));
        d += w;
        float2 hv = *(const float2*)&g_h1[(size_t)s * 64 + coff];
        acc.x = fmaf(hv.x, w, acc.x);
        acc.y = fmaf(hv.y, w, acc.y);
    }
    { // self loop
        float w = __expf(lrelu(an + ad));
        d += w;
        float2 hv = *(const float2*)&g_h1[(size_t)n * 64 + coff];
        acc.x = fmaf(hv.x, w, acc.x);
        acc.y = fmaf(hv.y, w, acc.y);
    }
    float inv = 1.f / (d + 1e-16f);
    float2 b = *(const float2*)&bias1[coff];
    float2 r = make_float2(acc.x * inv + b.x, acc.y * inv + b.y);
    *(float2*)&out[(size_t)n * 64 + coff] = r;
}

// ---------------- BatchNorm finalize ----------------------------------------
__global__ void k_bnfinal(const float* __restrict__ gamma, const float* __restrict__ beta) {
    int c = threadIdx.x;
    float mu = g_bnsum[c] / (float)NN;
    float var = g_bnsq[c] / (float)NN - mu * mu;
    float sc = gamma[c] * rsqrtf(var + 1e-5f);
    g_scale[c] = sc;
    g_shift[c] = beta[c] - mu * sc;
}

// ---------------- launch ----------------------------------------------------
extern "C" void kernel_launch(void* const* d_in, const int* in_sizes, int n_in,
                              void* d_out, int out_size) {
    const float* data = (const float*)d_in[0];
    const int*   ei   = (const int*)d_in[1];    // int32 (JAX x64 disabled)
    const float* W0   = (const float*)d_in[2];
    const float* as0  = (const float*)d_in[3];
    const float* ad0  = (const float*)d_in[4];
    const float* b0   = (const float*)d_in[5];
    const float* g0   = (const float*)d_in[6];
    const float* be0  = (const float*)d_in[7];
    const float* W1   = (const float*)d_in[8];
    const float* as1  = (const float*)d_in[9];
    const float* ad1  = (const float*)d_in[10];
    const float* b1   = (const float*)d_in[11];
    float* out = (float*)d_out;

    int E = in_sizes[1] / 2;
    if (E > EMAX) E = EMAX;

    int warpBlocks = (NN * 32 + 255) / 256;

    k_zero<<<(NN + 255) / 256, 256>>>();
    k_count<<<(E + 255) / 256, 256>>>(ei, E);
    k_scan<<<1, 1024>>>();
    k_scatter<<<(E + 255) / 256, 256>>>(ei, E);

    k_gemm<128, false><<<(NN + 127) / 128, 256>>>(data, W0, as0, ad0, NN);
    k_agg0<<<warpBlocks, 256>>>(b0);
    k_bnfinal<<<1, 128>>>(g0, be0);

    k_gemm<64, true><<<(NN + 127) / 128, 256>>>(nullptr, W1, as1, ad1, NN);
    k_agg1<<<warpBlocks, 256>>>(b1, out);
}

// round 5
// speedup vs baseline: 1.1844x; 1.1178x over previous
#include <cuda_runtime.h>
#include <cuda_fp16.h>
#include <math.h>

#define NN   50000
#define C0   128      // HEADS*HID
#define OUTC 64
#define EMAX 800000
#define NEG  0.2f

// ---------------- scratch (static device globals; no allocation) ------------
__device__ __align__(16) int    g_deg[NN];
__device__ __align__(16) int    g_off[NN + 4];
__device__ __align__(16) int    g_cur[NN];
__device__ __align__(16) int    g_csr[EMAX];
__device__ __align__(16) __half g_h0h[(size_t)NN * C0];
__device__ __align__(16) __half g_h1h[(size_t)NN * OUTC];
__device__ __align__(16) float  g_as0[NN * 2];
__device__ __align__(16) float  g_ad0[NN * 2];
__device__ __align__(16) float  g_agg0[(size_t)NN * C0];
__device__ __align__(16) float  g_bnsum[C0];
__device__ __align__(16) float  g_bnsq[C0];
__device__ __align__(16) float  g_a1s[NN];
__device__ __align__(16) float  g_a1d[NN];

// ---------------- CSR build -------------------------------------------------
__global__ void k_zero() {
    int i = blockIdx.x * blockDim.x + threadIdx.x;
    if (i < NN) g_deg[i] = 0;
    if (i < C0) { g_bnsum[i] = 0.f; g_bnsq[i] = 0.f; }
}

__global__ void k_count(const int* __restrict__ ei, int E) {
    int i = blockIdx.x * blockDim.x + threadIdx.x;
    if (i < E) {
        int d = ei[E + i];
        if (d >= 0 && d < NN) atomicAdd(&g_deg[d], 1);
    }
}

__global__ void k_scan() {
    __shared__ int part[1024];
    int t = threadIdx.x;
    const int chunk = (NN + 1023) / 1024;
    int beg = t * chunk;
    int end = min(beg + chunk, NN);
    int s = 0;
    for (int i = beg; i < end; i++) s += g_deg[i];
    part[t] = s;
    __syncthreads();
    for (int d = 1; d < 1024; d <<= 1) {
        int v = 0;
        if (t >= d) v = part[t - d];
        __syncthreads();
        part[t] += v;
        __syncthreads();
    }
    int base = (t == 0) ? 0 : part[t - 1];
    for (int i = beg; i < end; i++) {
        g_off[i] = base; g_cur[i] = base; base += g_deg[i];
    }
    if (t == 1023) g_off[NN] = part[1023];
}

__global__ void k_scatter(const int* __restrict__ ei, int E) {
    int i = blockIdx.x * blockDim.x + threadIdx.x;
    if (i < E) {
        int d = ei[E + i];
        int s = ei[i];
        if (d >= 0 && d < NN && s >= 0 && s < NN) {
            int p = atomicAdd(&g_cur[d], 1);
            g_csr[p] = s;
        }
    }
}

// ---------------- SGEMM (K = 128 fixed) + fused epilogue --------------------
// BNCOLS=128: layer 0, h -> g_h0h (fp16), logits -> g_as0/g_ad0 (2 heads).
// BNCOLS=64:  layer 1, h -> g_h1h (fp16), logits -> g_a1s/g_a1d (1 head).
// TRANS: A is g_agg0 with fused BatchNorm (stats from g_bnsum/g_bnsq) + ELU.
template <int BNCOLS, bool TRANS>
__global__ __launch_bounds__(256) void k_gemm(const float* __restrict__ Ax,
                                              const float* __restrict__ W,
                                              const float* __restrict__ att_s,
                                              const float* __restrict__ att_d,
                                              const float* __restrict__ gamma,
                                              const float* __restrict__ beta,
                                              int nrows) {
    const int TN = BNCOLS / 16;          // 8 or 4
    __shared__ float As[8][128];
    __shared__ float Bs[8][BNCOLS];
    __shared__ float sSc[128], sSh[128];
    const float* A = TRANS ? g_agg0 : Ax;

    int tid = threadIdx.x;
    int row0 = blockIdx.x * 128;
    int ty = tid / 16, tx = tid % 16;

    if (TRANS) {   // BatchNorm finalize, per-block (reads global stats)
        if (tid < 128) {
            float mu = g_bnsum[tid] / (float)NN;
            float var = g_bnsq[tid] / (float)NN - mu * mu;
            float sc = gamma[tid] * rsqrtf(var + 1e-5f);
            sSc[tid] = sc;
            sSh[tid] = beta[tid] - mu * sc;
        }
        __syncthreads();
    }

    float acc[8][TN];
#pragma unroll
    for (int i = 0; i < 8; i++)
#pragma unroll
        for (int j = 0; j < TN; j++) acc[i][j] = 0.f;

    for (int kk = 0; kk < 128; kk += 8) {
        {
            int ar = tid >> 1;
            int ak = (tid & 1) * 4;
            int grow = row0 + ar;
            float4 v = make_float4(0.f, 0.f, 0.f, 0.f);
            if (grow < nrows)
                v = *(const float4*)&A[(size_t)grow * 128 + kk + ak];
            if (TRANS) {
                int c = kk + ak;
                float t0 = v.x * sSc[c] + sSh[c];
                float t1 = v.y * sSc[c + 1] + sSh[c + 1];
                float t2 = v.z * sSc[c + 2] + sSh[c + 2];
                float t3 = v.w * sSc[c + 3] + sSh[c + 3];
                v.x = t0 > 0.f ? t0 : expm1f(t0);
                v.y = t1 > 0.f ? t1 : expm1f(t1);
                v.z = t2 > 0.f ? t2 : expm1f(t2);
                v.w = t3 > 0.f ? t3 : expm1f(t3);
            }
            As[ak + 0][ar] = v.x; As[ak + 1][ar] = v.y;
            As[ak + 2][ar] = v.z; As[ak + 3][ar] = v.w;
        }
        if (BNCOLS == 128) {
            int bk = tid >> 5, bc = (tid & 31) * 4;
            float4 v = *(const float4*)&W[(size_t)(kk + bk) * BNCOLS + bc];
            *(float4*)&Bs[bk][bc] = v;
        } else {
            int bk = tid >> 5, bc = (tid & 31) * 2;
            float2 v = *(const float2*)&W[(size_t)(kk + bk) * BNCOLS + bc];
            Bs[bk][bc] = v.x; Bs[bk][bc + 1] = v.y;
        }
        __syncthreads();
#pragma unroll
        for (int k = 0; k < 8; k++) {
            float ra[8], rb[TN];
#pragma unroll
            for (int i = 0; i < 8; i++) ra[i] = As[k][ty * 8 + i];
#pragma unroll
            for (int j = 0; j < TN; j++) rb[j] = Bs[k][tx * TN + j];
#pragma unroll
            for (int i = 0; i < 8; i++)
#pragma unroll
                for (int j = 0; j < TN; j++) acc[i][j] = fmaf(ra[i], rb[j], acc[i][j]);
        }
        __syncthreads();
    }

    float vs[TN], vd[TN];
#pragma unroll
    for (int j = 0; j < TN; j++) {
        vs[j] = att_s[tx * TN + j];
        vd[j] = att_d[tx * TN + j];
    }

#pragma unroll
    for (int i = 0; i < 8; i++) {
        int r = row0 + ty * 8 + i;
        bool ok = (r < nrows);
        if (ok) {   // fp16 feature store
            if (BNCOLS == 128) {
                __half2 hp[4];
#pragma unroll
                for (int j = 0; j < 4; j++)
                    hp[j] = __floats2half2_rn(acc[i][2 * j], acc[i][2 * j + 1]);
                *(uint4*)&g_h0h[(size_t)r * 128 + tx * 8] = *(uint4*)hp;
            } else {
                __half2 hp[2];
                hp[0] = __floats2half2_rn(acc[i][0], acc[i][1]);
                hp[1] = __floats2half2_rn(acc[i][2], acc[i][3]);
                *(uint2*)&g_h1h[(size_t)r * 64 + tx * 4] = *(uint2*)hp;
            }
        }
        // fused attention logits
        float ps = 0.f, pd = 0.f;
#pragma unroll
        for (int j = 0; j < TN; j++) {
            ps = fmaf(acc[i][j], vs[j], ps);
            pd = fmaf(acc[i][j], vd[j], pd);
        }
        if (BNCOLS == 128) {
#pragma unroll
            for (int o = 4; o; o >>= 1) {
                ps += __shfl_down_sync(0xffffffffu, ps, o, 8);
                pd += __shfl_down_sync(0xffffffffu, pd, o, 8);
            }
            if (ok && (tx & 7) == 0) {
                g_as0[r * 2 + (tx >> 3)] = ps;
                g_ad0[r * 2 + (tx >> 3)] = pd;
            }
        } else {
#pragma unroll
            for (int o = 8; o; o >>= 1) {
                ps += __shfl_down_sync(0xffffffffu, ps, o, 16);
                pd += __shfl_down_sync(0xffffffffu, pd, o, 16);
            }
            if (ok && tx == 0) {
                g_a1s[r] = ps;
                g_a1d[r] = pd;
            }
        }
    }
}

// ---------------- single-pass softmax-aggregate (warp per node) -------------
__device__ __forceinline__ float lrelu(float x) { return x > 0.f ? x : NEG * x; }

__global__ __launch_bounds__(256) void k_agg0(const float* __restrict__ bias0) {
    __shared__ float s_sum[C0];
    __shared__ float s_sq[C0];
    int tid = threadIdx.x;
    if (tid < C0) { s_sum[tid] = 0.f; s_sq[tid] = 0.f; }
    __syncthreads();

    int n = (blockIdx.x * blockDim.x + tid) >> 5;
    int lane = tid & 31;
    if (n < NN) {
        int beg = g_off[n], end = g_off[n + 1];
        float2 ad = *(const float2*)&g_ad0[n * 2];
        float2 an = *(const float2*)&g_as0[n * 2];
        bool head1 = lane >= 16;
        float adh = head1 ? ad.y : ad.x;
        float anh = head1 ? an.y : an.x;
        int coff = lane * 4;

        float d = 0.f;
        float4 acc = make_float4(0.f, 0.f, 0.f, 0.f);
#pragma unroll 2
        for (int i = beg; i < end; i++) {
            int s = g_csr[i];
            float2 a = *(const float2*)&g_as0[s * 2];
            float w = __expf(lrelu((head1 ? a.y : a.x) + adh));
            d += w;
            uint2 u = *(const uint2*)&g_h0h[(size_t)s * 128 + coff];
            float2 p0 = __half22float2(*(__half2*)&u.x);
            float2 p1 = __half22float2(*(__half2*)&u.y);
            acc.x = fmaf(p0.x, w, acc.x); acc.y = fmaf(p0.y, w, acc.y);
            acc.z = fmaf(p1.x, w, acc.z); acc.w = fmaf(p1.y, w, acc.w);
        }
        { // self loop
            float w = __expf(lrelu(anh + adh));
            d += w;
            uint2 u = *(const uint2*)&g_h0h[(size_t)n * 128 + coff];
            float2 p0 = __half22float2(*(__half2*)&u.x);
            float2 p1 = __half22float2(*(__half2*)&u.y);
            acc.x = fmaf(p0.x, w, acc.x); acc.y = fmaf(p0.y, w, acc.y);
            acc.z = fmaf(p1.x, w, acc.z); acc.w = fmaf(p1.y, w, acc.w);
        }
        float inv = 1.f / (d + 1e-16f);
        float4 b = *(const float4*)&bias0[coff];
        float4 o;
        o.x = acc.x * inv + b.x; o.y = acc.y * inv + b.y;
        o.z = acc.z * inv + b.z; o.w = acc.w * inv + b.w;
        *(float4*)&g_agg0[(size_t)n * 128 + coff] = o;

        atomicAdd(&s_sum[coff + 0], o.x); atomicAdd(&s_sq[coff + 0], o.x * o.x);
        atomicAdd(&s_sum[coff + 1], o.y); atomicAdd(&s_sq[coff + 1], o.y * o.y);
        atomicAdd(&s_sum[coff + 2], o.z); atomicAdd(&s_sq[coff + 2], o.z * o.z);
        atomicAdd(&s_sum[coff + 3], o.w); atomicAdd(&s_sq[coff + 3], o.w * o.w);
    }
    __syncthreads();
    if (tid < C0) {
        atomicAdd(&g_bnsum[tid], s_sum[tid]);
        atomicAdd(&g_bnsq[tid], s_sq[tid]);
    }
}

__global__ __launch_bounds__(256) void k_agg1(const float* __restrict__ bias1,
                                              float* __restrict__ out) {
    int n = (blockIdx.x * blockDim.x + threadIdx.x) >> 5;
    int lane = threadIdx.x & 31;
    if (n >= NN) return;
    int beg = g_off[n], end = g_off[n + 1];
    float ad = g_a1d[n];
    float an = g_a1s[n];
    int coff = lane * 2;

    float d = 0.f;
    float2 acc = make_float2(0.f, 0.f);
#pragma unroll 2
    for (int i = beg; i < end; i++) {
        int s = g_csr[i];
        float w = __expf(lrelu(g_a1s[s] + ad));
        d += w;
        unsigned u = *(const unsigned*)&g_h1h[(size_t)s * 64 + coff];
        float2 p = __half22float2(*(__half2*)&u);
        acc.x = fmaf(p.x, w, acc.x);
        acc.y = fmaf(p.y, w, acc.y);
    }
    { // self loop
        float w = __expf(lrelu(an + ad));
        d += w;
        unsigned u = *(const unsigned*)&g_h1h[(size_t)n * 64 + coff];
        float2 p = __half22float2(*(__half2*)&u);
        acc.x = fmaf(p.x, w, acc.x);
        acc.y = fmaf(p.y, w, acc.y);
    }
    float inv = 1.f / (d + 1e-16f);
    float2 b = *(const float2*)&bias1[coff];
    float2 r = make_float2(acc.x * inv + b.x, acc.y * inv + b.y);
    *(float2*)&out[(size_t)n * 64 + coff] = r;
}

// ---------------- launch ----------------------------------------------------
extern "C" void kernel_launch(void* const* d_in, const int* in_sizes, int n_in,
                              void* d_out, int out_size) {
    const float* data = (const float*)d_in[0];
    const int*   ei   = (const int*)d_in[1];    // int32 (JAX x64 disabled)
    const float* W0   = (const float*)d_in[2];
    const float* as0  = (const float*)d_in[3];
    const float* ad0  = (const float*)d_in[4];
    const float* b0   = (const float*)d_in[5];
    const float* g0   = (const float*)d_in[6];
    const float* be0  = (const float*)d_in[7];
    const float* W1   = (const float*)d_in[8];
    const float* as1  = (const float*)d_in[9];
    const float* ad1  = (const float*)d_in[10];
    const float* b1   = (const float*)d_in[11];
    float* out = (float*)d_out;

    int E = in_sizes[1] / 2;
    if (E > EMAX) E = EMAX;

    int warpBlocks = (NN * 32 + 255) / 256;

    // side stream + events for CSR build || GEMM0 (created once; reused)
    static cudaStream_t s2 = nullptr;
    static cudaEvent_t evFork = nullptr, evJoin = nullptr;
    if (!s2) {
        cudaStreamCreateWithFlags(&s2, cudaStreamNonBlocking);
        cudaEventCreateWithFlags(&evFork, cudaEventDisableTiming);
        cudaEventCreateWithFlags(&evJoin, cudaEventDisableTiming);
    }

    // fork: CSR chain on s2
    cudaEventRecord(evFork, 0);
    cudaStreamWaitEvent(s2, evFork, 0);
    k_zero<<<(NN + 255) / 256, 256, 0, s2>>>();
    k_count<<<(E + 255) / 256, 256, 0, s2>>>(ei, E);
    k_scan<<<1, 1024, 0, s2>>>();
    k_scatter<<<(E + 255) / 256, 256, 0, s2>>>(ei, E);
    cudaEventRecord(evJoin, s2);

    // main stream: GEMM0 (independent of CSR)
    k_gemm<128, false><<<(NN + 127) / 128, 256>>>(data, W0, as0, ad0, nullptr, nullptr, NN);

    // join, then the dependent chain
    cudaStreamWaitEvent(0, evJoin, 0);
    k_agg0<<<warpBlocks, 256>>>(b0);
    k_gemm<64, true><<<(NN + 127) / 128, 256>>>(nullptr, W1, as1, ad1, g0, be0, NN);
    k_agg1<<<warpBlocks, 256>>>(b1, out);
}